// round 16
// baseline (speedup 1.0000x reference)
#include <cuda_runtime.h>
#include <cuda_fp16.h>
#include <stdint.h>

#define NN 100000
#define F_IN 512
#define F_HID 128
#define F_OUT 64
#define BCAP 128   // per-node in-edge bucket capacity

// ---------------- scratch (static device arrays) --------------------------------
__device__ __align__(16) uint8_t g_xw1q[(size_t)NN * F_HID];  // x@W1 (UNscaled), e4m3
__device__ __align__(16) __half  g_h16[(size_t)NN * F_HID];   // relu'd hidden, fp16
__device__ __align__(16) uint8_t g_xw2q[(size_t)NN * F_OUT];  // (h@W2)*dinv[row], e4m3
__device__ __align__(16) int     g_bucket[(size_t)NN * BCAP];
__device__ __align__(16) int     g_cnt[NN];
__device__ __align__(16) float   g_dinv[NN];
__device__ __align__(16) __half  g_w1h[F_HID * F_IN];         // W1^T [n][k], fp16
__device__ __align__(16) __half  g_w2h[F_OUT * F_HID];        // W2^T [n][k], fp16
__device__ int g_is32;

// ---------------- fp16 tensor-core mma + ldmatrix --------------------------------
__device__ __forceinline__ void mma_f16(float* d, const uint32_t* a, const uint32_t* b) {
    asm volatile(
        "mma.sync.aligned.m16n8k16.row.col.f32.f16.f16.f32 "
        "{%0,%1,%2,%3}, {%4,%5,%6,%7}, {%8,%9}, {%0,%1,%2,%3};"
        : "+f"(d[0]), "+f"(d[1]), "+f"(d[2]), "+f"(d[3])
        : "r"(a[0]), "r"(a[1]), "r"(a[2]), "r"(a[3]), "r"(b[0]), "r"(b[1]));
}

__device__ __forceinline__ void ldsm_x4(uint32_t& r0, uint32_t& r1, uint32_t& r2,
                                        uint32_t& r3, uint32_t addr) {
    asm volatile("ldmatrix.sync.aligned.m8n8.x4.shared.b16 {%0,%1,%2,%3}, [%4];"
                 : "=r"(r0), "=r"(r1), "=r"(r2), "=r"(r3) : "r"(addr));
}

// ---- fp8 helpers ----
__device__ __forceinline__ uint16_t pack_e4m3x2(float lo, float hi) {
    uint16_t p;
    asm("cvt.rn.satfinite.e4m3x2.f32 %0, %1, %2;" : "=h"(p) : "f"(hi), "f"(lo));
    return p;
}
__device__ __forceinline__ void dq16(uint4 u, float* f) {
    const uint32_t w[4] = {u.x, u.y, u.z, u.w};
#pragma unroll
    for (int i = 0; i < 4; i++) {
        uint16_t lo = (uint16_t)w[i];
        uint16_t hi = (uint16_t)(w[i] >> 16);
        uint32_t h2a, h2b;
        asm("cvt.rn.f16x2.e4m3x2 %0, %1;" : "=r"(h2a) : "h"(lo));
        asm("cvt.rn.f16x2.e4m3x2 %0, %1;" : "=r"(h2b) : "h"(hi));
        float2 fa = __half22float2(*(__half2*)&h2a);
        float2 fb = __half22float2(*(__half2*)&h2b);
        f[i * 4 + 0] = fa.x; f[i * 4 + 1] = fa.y;
        f[i * 4 + 2] = fb.x; f[i * 4 + 3] = fb.y;
    }
}

// ---------------- setup kernels ---------------------------------------------------
__global__ void init_kernel(const int* __restrict__ w) {
    int i = blockIdx.x * blockDim.x + threadIdx.x;
    if (i < NN) g_cnt[i] = 0;
    if (i == 0) g_is32 = 0;
    if (i < 2048 && w[2 * i + 1] != 0) g_is32 = 1;
}

__global__ void fill_kernel(const int* __restrict__ w, int E) {
    int i = (blockIdx.x * blockDim.x + threadIdx.x) * 2;
    if (i >= E) return;
    int s0, s1, d0, d1;
    if (g_is32) {
        int2 sp = *(const int2*)&w[i];
        int2 dp = *(const int2*)&w[E + i];
        s0 = sp.x; s1 = sp.y; d0 = dp.x; d1 = dp.y;
    } else {
        int4 sp = *(const int4*)&w[2 * (size_t)i];
        int4 dp = *(const int4*)&w[2 * ((size_t)E + i)];
        s0 = sp.x; s1 = sp.z; d0 = dp.x; d1 = dp.z;
    }
    if ((unsigned)s0 >= NN) s0 = 0;
    if ((unsigned)s1 >= NN) s1 = 0;
    if ((unsigned)d0 >= NN) d0 = 0;
    if ((unsigned)d1 >= NN) d1 = 0;
    int p0 = atomicAdd(&g_cnt[d0], 1);
    if (p0 < BCAP) g_bucket[(size_t)d0 * BCAP + p0] = s0;
    int p1 = atomicAdd(&g_cnt[d1], 1);
    if (p1 < BCAP) g_bucket[(size_t)d1 * BCAP + p1] = s1;
}

__global__ void dinv_kernel(int n) {
    int i = blockIdx.x * blockDim.x + threadIdx.x;
    if (i < n) g_dinv[i] = rsqrtf((float)(g_cnt[i] + 1));
}

__global__ void wconv(const float* __restrict__ W1, const float* __restrict__ W2) {
    int i = blockIdx.x * blockDim.x + threadIdx.x;
    if (i < F_IN * F_HID) {
        int k = i / F_HID, nn = i % F_HID;
        g_w1h[nn * F_IN + k] = __float2half_rn(W1[i]);
    }
    if (i < F_HID * F_OUT) {
        int k = i / F_OUT, nn = i % F_OUT;
        g_w2h[nn * F_HID + k] = __float2half_rn(W2[i]);
    }
}

#define ASTR 40   // fp16 row stride in smem (80B: (20r)%32 banks distinct -> LDSM clean)

// ---------------- layer-1 GEMM (fp16 TC, double-buffered, ldmatrix, fp8 out) -----
__global__ void __launch_bounds__(256, 2)
gemm1_mma(const float* __restrict__ A, uint8_t* __restrict__ C, int M) {
    __shared__ __align__(16) __half Ah[2][128 * ASTR];
    __shared__ __align__(16) __half Bh[2][128 * ASTR];

    const int tid = threadIdx.x;
    const int wid = tid >> 5;
    const int lane = tid & 31;
    const int warpM = (wid >> 2) * 64;
    const int warpN = (wid & 3) * 32;
    const int rowBase = blockIdx.x * 128;
    const int grp = lane >> 2;
    const int qid = lane & 3;
    constexpr int NT = F_IN / 32;

    const int a_row = (lane & 7) + ((lane >> 3) & 1) * 8;
    const int a_col = (lane >> 4) * 8;
    const int b_row = (lane & 7) + (lane >> 4) * 8;
    const int b_col = ((lane >> 3) & 1) * 8;
    const uint32_t aBase0 = (uint32_t)__cvta_generic_to_shared(&Ah[0][0]);
    const uint32_t aBase1 = (uint32_t)__cvta_generic_to_shared(&Ah[1][0]);
    const uint32_t bBase0 = (uint32_t)__cvta_generic_to_shared(&Bh[0][0]);
    const uint32_t bBase1 = (uint32_t)__cvta_generic_to_shared(&Bh[1][0]);

    int ar[4], ac[4];
#pragma unroll
    for (int t = 0; t < 4; t++) {
        int idx = tid + t * 256;
        ar[t] = idx >> 3;
        ac[t] = (idx & 7) * 4;
    }
    int bn[2], bk[2];
#pragma unroll
    for (int t = 0; t < 2; t++) {
        int idx = tid + t * 256;
        bn[t] = idx >> 2;
        bk[t] = (idx & 3) * 8;
    }

    float acc[4][4][4];
#pragma unroll
    for (int mi = 0; mi < 4; mi++)
#pragma unroll
        for (int nj = 0; nj < 4; nj++)
#pragma unroll
            for (int q = 0; q < 4; q++) acc[mi][nj][q] = 0.f;

    {
#pragma unroll
        for (int t = 0; t < 4; t++) {
            int gr = rowBase + ar[t];
            float4 v = make_float4(0.f, 0.f, 0.f, 0.f);
            if (gr < M) v = *(const float4*)&A[(size_t)gr * F_IN + ac[t]];
            __half2 p0 = __floats2half2_rn(v.x, v.y);
            __half2 p1 = __floats2half2_rn(v.z, v.w);
            uint32_t* ph = (uint32_t*)&Ah[0][ar[t] * ASTR + ac[t]];
            ph[0] = *(uint32_t*)&p0;
            ph[1] = *(uint32_t*)&p1;
        }
#pragma unroll
        for (int t = 0; t < 2; t++)
            *(int4*)&Bh[0][bn[t] * ASTR + bk[t]] = *(const int4*)&g_w1h[bn[t] * F_IN + bk[t]];
    }
    __syncthreads();

    for (int kt = 0; kt < NT; kt++) {
        const int cur = kt & 1;
        const int k1 = (kt + 1) * 32;
        const uint32_t aB = cur ? aBase1 : aBase0;
        const uint32_t bB = cur ? bBase1 : bBase0;

        float4 vA[4];
        int4 vB[2];
        if (kt + 1 < NT) {
#pragma unroll
            for (int t = 0; t < 4; t++) {
                int gr = rowBase + ar[t];
                vA[t] = make_float4(0.f, 0.f, 0.f, 0.f);
                if (gr < M) vA[t] = *(const float4*)&A[(size_t)gr * F_IN + k1 + ac[t]];
            }
#pragma unroll
            for (int t = 0; t < 2; t++)
                vB[t] = *(const int4*)&g_w1h[bn[t] * F_IN + k1 + bk[t]];
        }

#pragma unroll
        for (int ks = 0; ks < 2; ks++) {
            const int kst = ks * 16;
            uint32_t ah[4][4];
#pragma unroll
            for (int mi = 0; mi < 4; mi++) {
                uint32_t addr = aB + (uint32_t)(((warpM + mi * 16 + a_row) * ASTR
                                                 + kst + a_col) * 2);
                ldsm_x4(ah[mi][0], ah[mi][1], ah[mi][2], ah[mi][3], addr);
            }
            uint32_t bh[4][2];
#pragma unroll
            for (int njp = 0; njp < 2; njp++) {
                uint32_t addr = bB + (uint32_t)(((warpN + njp * 16 + b_row) * ASTR
                                                 + kst + b_col) * 2);
                ldsm_x4(bh[2 * njp][0], bh[2 * njp][1],
                        bh[2 * njp + 1][0], bh[2 * njp + 1][1], addr);
            }
#pragma unroll
            for (int mi = 0; mi < 4; mi++)
#pragma unroll
                for (int nj = 0; nj < 4; nj++)
                    mma_f16(acc[mi][nj], ah[mi], bh[nj]);
        }

        if (kt + 1 < NT) {
            const int nxt = cur ^ 1;
#pragma unroll
            for (int t = 0; t < 4; t++) {
                __half2 p0 = __floats2half2_rn(vA[t].x, vA[t].y);
                __half2 p1 = __floats2half2_rn(vA[t].z, vA[t].w);
                uint32_t* ph = (uint32_t*)&Ah[nxt][ar[t] * ASTR + ac[t]];
                ph[0] = *(uint32_t*)&p0;
                ph[1] = *(uint32_t*)&p1;
            }
#pragma unroll
            for (int t = 0; t < 2; t++)
                *(int4*)&Bh[nxt][bn[t] * ASTR + bk[t]] = vB[t];
            __syncthreads();
        }
    }

    // ---- epilogue: store e4m3 (unscaled) ----
#pragma unroll
    for (int mi = 0; mi < 4; mi++) {
        int r0 = rowBase + warpM + mi * 16 + grp;
        int r1 = r0 + 8;
#pragma unroll
        for (int nj = 0; nj < 4; nj++) {
            int c = warpN + nj * 8 + qid * 2;
            if (r0 < M)
                *(uint16_t*)&C[(size_t)r0 * F_HID + c] =
                    pack_e4m3x2(acc[mi][nj][0], acc[mi][nj][1]);
            if (r1 < M)
                *(uint16_t*)&C[(size_t)r1 * F_HID + c] =
                    pack_e4m3x2(acc[mi][nj][2], acc[mi][nj][3]);
        }
    }
}

// ---------------- layer-2 GEMM (fp16 TC, chunked, ldmatrix, fp8 out) -------------
__global__ void __launch_bounds__(256, 2)
gemm2_mma(uint8_t* __restrict__ C, int rowOff, int rowEnd) {
    __shared__ __align__(16) __half Ah[128 * ASTR];
    __shared__ __align__(16) __half Bh[64 * ASTR];

    const int tid = threadIdx.x;
    const int wid = tid >> 5;
    const int lane = tid & 31;
    const int warpM = (wid >> 2) * 64;
    const int warpN = (wid & 3) * 16;
    const int rowBase = rowOff + blockIdx.x * 128;
    const int grp = lane >> 2;
    const int qid = lane & 3;

    const int a_row = (lane & 7) + ((lane >> 3) & 1) * 8;
    const int a_col = (lane >> 4) * 8;
    const int b_row = (lane & 7) + (lane >> 4) * 8;
    const int b_col = ((lane >> 3) & 1) * 8;
    const uint32_t aBase = (uint32_t)__cvta_generic_to_shared(&Ah[0]);
    const uint32_t bBase = (uint32_t)__cvta_generic_to_shared(&Bh[0]);

    float acc[4][2][4];
#pragma unroll
    for (int mi = 0; mi < 4; mi++)
#pragma unroll
        for (int nj = 0; nj < 2; nj++)
#pragma unroll
            for (int q = 0; q < 4; q++) acc[mi][nj][q] = 0.f;

    for (int k0 = 0; k0 < F_HID; k0 += 32) {
#pragma unroll
        for (int t = 0; t < 2; t++) {
            int idx = tid + t * 256;
            int r = idx >> 2;
            int koff = (idx & 3) * 8;
            int gr = rowBase + r;
            uint4 v = make_uint4(0u, 0u, 0u, 0u);
            if (gr < rowEnd) v = *(const uint4*)&g_h16[(size_t)gr * F_HID + k0 + koff];
            *(uint4*)&Ah[r * ASTR + koff] = v;
        }
        if (tid < 256) {
            int nrow = tid >> 2;
            int koff = (tid & 3) * 8;
            *(int4*)&Bh[nrow * ASTR + koff] = *(const int4*)&g_w2h[nrow * F_HID + k0 + koff];
        }
        __syncthreads();

#pragma unroll
        for (int ks = 0; ks < 2; ks++) {
            const int kst = ks * 16;
            uint32_t ah[4][4];
#pragma unroll
            for (int mi = 0; mi < 4; mi++) {
                uint32_t addr = aBase + (uint32_t)(((warpM + mi * 16 + a_row) * ASTR
                                                    + kst + a_col) * 2);
                ldsm_x4(ah[mi][0], ah[mi][1], ah[mi][2], ah[mi][3], addr);
            }
            uint32_t bh[2][2];
            {
                uint32_t addr = bBase + (uint32_t)(((warpN + b_row) * ASTR
                                                    + kst + b_col) * 2);
                ldsm_x4(bh[0][0], bh[0][1], bh[1][0], bh[1][1], addr);
            }
#pragma unroll
            for (int mi = 0; mi < 4; mi++)
#pragma unroll
                for (int nj = 0; nj < 2; nj++)
                    mma_f16(acc[mi][nj], ah[mi], bh[nj]);
        }
        __syncthreads();
    }

#pragma unroll
    for (int mi = 0; mi < 4; mi++) {
        int r0 = rowBase + warpM + mi * 16 + grp;
        int r1 = r0 + 8;
        float s0 = (r0 < rowEnd) ? g_dinv[r0] : 0.f;
        float s1 = (r1 < rowEnd) ? g_dinv[r1] : 0.f;
#pragma unroll
        for (int nj = 0; nj < 2; nj++) {
            int c = warpN + nj * 8 + qid * 2;
            if (r0 < rowEnd)
                *(uint16_t*)&C[(size_t)r0 * F_OUT + c] =
                    pack_e4m3x2(acc[mi][nj][0] * s0, acc[mi][nj][1] * s0);
            if (r1 < rowEnd)
                *(uint16_t*)&C[(size_t)r1 * F_OUT + c] =
                    pack_e4m3x2(acc[mi][nj][2] * s1, acc[mi][nj][3] * s1);
        }
    }
}

// ---------------- gather layer 1: 8 lanes/node (fp8 rows), fused bias+relu -------
__global__ void gather1(const float* __restrict__ b1, int nodeOff, int nodeEnd) {
    size_t t = (size_t)blockIdx.x * blockDim.x + threadIdx.x;
    int node = nodeOff + (int)(t >> 3);
    int l = threadIdx.x & 7;
    if (node >= nodeEnd) return;
    const uint4* xw1 = (const uint4*)g_xw1q;
    float di = g_dinv[node];
    float acc[16], v[16];
    dq16(xw1[(size_t)node * 8 + l], acc);
#pragma unroll
    for (int q = 0; q < 16; q++) acc[q] *= di;
    int ne = g_cnt[node];
    if (ne > BCAP) ne = BCAP;
    int base = node * BCAP;
    int i = 0;
    for (; i + 4 <= ne; i += 4) {
        int4 s4 = *(const int4*)&g_bucket[base + i];
        uint4 r0 = xw1[(size_t)s4.x * 8 + l];
        uint4 r1 = xw1[(size_t)s4.y * 8 + l];
        uint4 r2 = xw1[(size_t)s4.z * 8 + l];
        uint4 r3 = xw1[(size_t)s4.w * 8 + l];
        float d0 = g_dinv[s4.x], d1 = g_dinv[s4.y], d2 = g_dinv[s4.z], d3 = g_dinv[s4.w];
        dq16(r0, v);
#pragma unroll
        for (int q = 0; q < 16; q++) acc[q] = fmaf(d0, v[q], acc[q]);
        dq16(r1, v);
#pragma unroll
        for (int q = 0; q < 16; q++) acc[q] = fmaf(d1, v[q], acc[q]);
        dq16(r2, v);
#pragma unroll
        for (int q = 0; q < 16; q++) acc[q] = fmaf(d2, v[q], acc[q]);
        dq16(r3, v);
#pragma unroll
        for (int q = 0; q < 16; q++) acc[q] = fmaf(d3, v[q], acc[q]);
    }
    for (; i < ne; i++) {
        int s = g_bucket[base + i];
        float ds = g_dinv[s];
        dq16(xw1[(size_t)s * 8 + l], v);
#pragma unroll
        for (int q = 0; q < 16; q++) acc[q] = fmaf(ds, v[q], acc[q]);
    }
    float bf[16];
#pragma unroll
    for (int k = 0; k < 4; k++) {
        float4 bv = ((const float4*)b1)[l * 4 + k];
        bf[k * 4 + 0] = bv.x; bf[k * 4 + 1] = bv.y;
        bf[k * 4 + 2] = bv.z; bf[k * 4 + 3] = bv.w;
    }
    __half2 out[8];
#pragma unroll
    for (int q = 0; q < 8; q++) {
        float h0 = fmaxf(fmaf(acc[2 * q], di, bf[2 * q]), 0.f);
        float h1 = fmaxf(fmaf(acc[2 * q + 1], di, bf[2 * q + 1]), 0.f);
        out[q] = __floats2half2_rn(h0, h1);
    }
    uint4* dst = (uint4*)&g_h16[(size_t)node * F_HID + l * 16];
    dst[0] = *(uint4*)&out[0];
    dst[1] = *(uint4*)&out[4];
}

// ---------------- gather layer 2: 4 lanes/node (fp8 rows), fused lsm -------------
__global__ void gather2_lsm(const float* __restrict__ b2, float* __restrict__ out, int n) {
    size_t t = (size_t)blockIdx.x * blockDim.x + threadIdx.x;
    int node = (int)(t >> 2);
    int l = threadIdx.x & 3;
    if (node >= n) return;
    const uint4* xw2 = (const uint4*)g_xw2q;   // 4 uint4 per row (16 e4m3 each)
    float acc[16], v[16];
    dq16(xw2[(size_t)node * 4 + l], acc);      // self (pre-scaled by dinv[row])
    int ne = g_cnt[node];
    if (ne > BCAP) ne = BCAP;
    int base = node * BCAP;
    int i = 0;
    for (; i + 4 <= ne; i += 4) {
        int4 s4 = *(const int4*)&g_bucket[base + i];
        uint4 r0 = xw2[(size_t)s4.x * 4 + l];
        uint4 r1 = xw2[(size_t)s4.y * 4 + l];
        uint4 r2 = xw2[(size_t)s4.z * 4 + l];
        uint4 r3 = xw2[(size_t)s4.w * 4 + l];
        dq16(r0, v);
#pragma unroll
        for (int q = 0; q < 16; q++) acc[q] += v[q];
        dq16(r1, v);
#pragma unroll
        for (int q = 0; q < 16; q++) acc[q] += v[q];
        dq16(r2, v);
#pragma unroll
        for (int q = 0; q < 16; q++) acc[q] += v[q];
        dq16(r3, v);
#pragma unroll
        for (int q = 0; q < 16; q++) acc[q] += v[q];
    }
    for (; i < ne; i++) {
        dq16(xw2[(size_t)g_bucket[base + i] * 4 + l], v);
#pragma unroll
        for (int q = 0; q < 16; q++) acc[q] += v[q];
    }
    float di = g_dinv[node];
    float bf[16];
#pragma unroll
    for (int k = 0; k < 4; k++) {
        float4 bv = ((const float4*)b2)[l * 4 + k];
        bf[k * 4 + 0] = bv.x; bf[k * 4 + 1] = bv.y;
        bf[k * 4 + 2] = bv.z; bf[k * 4 + 3] = bv.w;
    }
    float z[16];
    float m = -1e30f;
#pragma unroll
    for (int q = 0; q < 16; q++) {
        z[q] = fmaf(acc[q], di, bf[q]);
        m = fmaxf(m, z[q]);
    }
#pragma unroll
    for (int o = 2; o; o >>= 1) m = fmaxf(m, __shfl_xor_sync(0xffffffffu, m, o));
    float s = 0.f;
#pragma unroll
    for (int q = 0; q < 16; q++) s += expf(z[q] - m);
#pragma unroll
    for (int o = 2; o; o >>= 1) s += __shfl_xor_sync(0xffffffffu, s, o);
    float lse = m + logf(s);
    float* op = &out[(size_t)node * F_OUT + l * 16];
#pragma unroll
    for (int k = 0; k < 4; k++) {
        float4 o4 = make_float4(z[k * 4 + 0] - lse, z[k * 4 + 1] - lse,
                                z[k * 4 + 2] - lse, z[k * 4 + 3] - lse);
        *(float4*)&op[k * 4] = o4;
    }
}

// ---------------- launch ----------------------------------------------------------
extern "C" void kernel_launch(void* const* d_in, const int* in_sizes, int n_in,
                              void* d_out, int out_size) {
    const float* x  = (const float*)d_in[0];
    const float* W1 = (const float*)d_in[1];
    const float* b1 = (const float*)d_in[2];
    const float* W2 = (const float*)d_in[3];
    const float* b2 = (const float*)d_in[4];
    const int* ei_words = (const int*)d_in[5];

    const int n = in_sizes[0] / F_IN;   // 100000
    const int E = in_sizes[5] / 2;      // 3200000

    uint8_t *xw1p, *xw2p;
    cudaGetSymbolAddress((void**)&xw1p, g_xw1q);
    cudaGetSymbolAddress((void**)&xw2p, g_xw2q);

    static cudaStream_t sB = nullptr;
    static cudaEvent_t evFork = nullptr, evJoin = nullptr;
    static cudaEvent_t evA1 = nullptr, evA2 = nullptr, evB = nullptr;
    if (!sB) {
        cudaStreamCreateWithFlags(&sB, cudaStreamNonBlocking);
        cudaEventCreateWithFlags(&evFork, cudaEventDisableTiming);
        cudaEventCreateWithFlags(&evJoin, cudaEventDisableTiming);
        cudaEventCreateWithFlags(&evA1, cudaEventDisableTiming);
        cudaEventCreateWithFlags(&evA2, cudaEventDisableTiming);
        cudaEventCreateWithFlags(&evB, cudaEventDisableTiming);
    }

    // Fork: edge pipeline overlapped with weight conversion + layer-1 GEMM.
    cudaEventRecord(evFork, 0);
    cudaStreamWaitEvent(sB, evFork, 0);

    init_kernel<<<(NN + 255) / 256, 256, 0, sB>>>(ei_words);
    fill_kernel<<<(E / 2 + 255) / 256, 256, 0, sB>>>(ei_words, E);
    dinv_kernel<<<(n + 255) / 256, 256, 0, sB>>>(n);
    cudaEventRecord(evJoin, sB);

    wconv<<<(F_IN * F_HID + 255) / 256, 256>>>(W1, W2);
    gemm1_mma<<<(n + 127) / 128, 256>>>(x, xw1p, n);

    cudaStreamWaitEvent(0, evJoin, 0);

    // ---- 3-chunk gather1 / gemm2 pipeline ----
    const int c1 = ((n / 3 + 127) / 128) * 128;      // 33408
    const int c2 = 2 * c1;                            // 66816
    {
        size_t th = (size_t)c1 * 8;
        gather1<<<(unsigned)((th + 255) / 256), 256>>>(b1, 0, c1);
    }
    cudaEventRecord(evA1, 0);
    cudaStreamWaitEvent(sB, evA1, 0);
    gemm2_mma<<<(c1 + 127) / 128, 256, 0, sB>>>(xw2p, 0, c1);
    {
        size_t th = (size_t)(c2 - c1) * 8;
        gather1<<<(unsigned)((th + 255) / 256), 256>>>(b1, c1, c2);
    }
    cudaEventRecord(evA2, 0);
    cudaStreamWaitEvent(sB, evA2, 0);
    gemm2_mma<<<(c2 - c1 + 127) / 128, 256, 0, sB>>>(xw2p, c1, c2);
    cudaEventRecord(evB, sB);
    {
        size_t th = (size_t)(n - c2) * 8;
        gather1<<<(unsigned)((th + 255) / 256), 256>>>(b1, c2, n);
    }
    gemm2_mma<<<(n - c2 + 127) / 128, 256>>>(xw2p, c2, n);
    cudaStreamWaitEvent(0, evB, 0);

    {
        size_t th = (size_t)n * 4;
        gather2_lsm<<<(unsigned)((th + 255) / 256), 256>>>(b2, (float*)d_out, n);
    }
}

// round 17
// speedup vs baseline: 1.0983x; 1.0983x over previous
#include <cuda_runtime.h>
#include <cuda_fp16.h>
#include <stdint.h>

#define NN 100000
#define F_IN 512
#define F_HID 128
#define F_OUT 64
#define BCAP 128   // per-node in-edge bucket capacity

// ---------------- scratch (static device arrays) --------------------------------
__device__ __align__(16) uint8_t g_xw1q[(size_t)NN * F_HID];  // x@W1 (UNscaled), e4m3
__device__ __align__(16) __half  g_h16[(size_t)NN * F_HID];   // relu'd hidden, fp16
__device__ __align__(16) __half  g_xw2h[(size_t)NN * F_OUT];  // (h@W2)*dinv[row], fp16
__device__ __align__(16) int     g_bucket[(size_t)NN * BCAP];
__device__ __align__(16) int     g_cnt[NN];
__device__ __align__(16) float   g_dinv[NN];
__device__ __align__(16) __half  g_w1h[F_HID * F_IN];         // W1^T [n][k], fp16
__device__ __align__(16) __half  g_w2h[F_OUT * F_HID];        // W2^T [n][k], fp16
__device__ int g_is32;

// ---------------- fp16 tensor-core mma + ldmatrix --------------------------------
__device__ __forceinline__ void mma_f16(float* d, const uint32_t* a, const uint32_t* b) {
    asm volatile(
        "mma.sync.aligned.m16n8k16.row.col.f32.f16.f16.f32 "
        "{%0,%1,%2,%3}, {%4,%5,%6,%7}, {%8,%9}, {%0,%1,%2,%3};"
        : "+f"(d[0]), "+f"(d[1]), "+f"(d[2]), "+f"(d[3])
        : "r"(a[0]), "r"(a[1]), "r"(a[2]), "r"(a[3]), "r"(b[0]), "r"(b[1]));
}

__device__ __forceinline__ void ldsm_x4(uint32_t& r0, uint32_t& r1, uint32_t& r2,
                                        uint32_t& r3, uint32_t addr) {
    asm volatile("ldmatrix.sync.aligned.m8n8.x4.shared.b16 {%0,%1,%2,%3}, [%4];"
                 : "=r"(r0), "=r"(r1), "=r"(r2), "=r"(r3) : "r"(addr));
}

// ---- fp8 helpers ----
__device__ __forceinline__ uint16_t pack_e4m3x2(float lo, float hi) {
    uint16_t p;
    asm("cvt.rn.satfinite.e4m3x2.f32 %0, %1, %2;" : "=h"(p) : "f"(hi), "f"(lo));
    return p;
}
// decode 16 e4m3 bytes -> 8 half2 (no unpack to fp32)
__device__ __forceinline__ void dq8h(uint4 u, __half2* h) {
    const uint32_t w[4] = {u.x, u.y, u.z, u.w};
#pragma unroll
    for (int i = 0; i < 4; i++) {
        uint16_t lo = (uint16_t)w[i];
        uint16_t hi = (uint16_t)(w[i] >> 16);
        uint32_t a, b;
        asm("cvt.rn.f16x2.e4m3x2 %0, %1;" : "=r"(a) : "h"(lo));
        asm("cvt.rn.f16x2.e4m3x2 %0, %1;" : "=r"(b) : "h"(hi));
        h[2 * i]     = *(__half2*)&a;
        h[2 * i + 1] = *(__half2*)&b;
    }
}

// ---------------- setup kernels ---------------------------------------------------
__global__ void init_kernel(const int* __restrict__ w) {
    int i = blockIdx.x * blockDim.x + threadIdx.x;
    if (i < NN) g_cnt[i] = 0;
    if (i == 0) g_is32 = 0;
    if (i < 2048 && w[2 * i + 1] != 0) g_is32 = 1;
}

__global__ void fill_kernel(const int* __restrict__ w, int E) {
    int i = (blockIdx.x * blockDim.x + threadIdx.x) * 2;
    if (i >= E) return;
    int s0, s1, d0, d1;
    if (g_is32) {
        int2 sp = *(const int2*)&w[i];
        int2 dp = *(const int2*)&w[E + i];
        s0 = sp.x; s1 = sp.y; d0 = dp.x; d1 = dp.y;
    } else {
        int4 sp = *(const int4*)&w[2 * (size_t)i];
        int4 dp = *(const int4*)&w[2 * ((size_t)E + i)];
        s0 = sp.x; s1 = sp.z; d0 = dp.x; d1 = dp.z;
    }
    if ((unsigned)s0 >= NN) s0 = 0;
    if ((unsigned)s1 >= NN) s1 = 0;
    if ((unsigned)d0 >= NN) d0 = 0;
    if ((unsigned)d1 >= NN) d1 = 0;
    int p0 = atomicAdd(&g_cnt[d0], 1);
    if (p0 < BCAP) g_bucket[(size_t)d0 * BCAP + p0] = s0;
    int p1 = atomicAdd(&g_cnt[d1], 1);
    if (p1 < BCAP) g_bucket[(size_t)d1 * BCAP + p1] = s1;
}

__global__ void dinv_kernel(int n) {
    int i = blockIdx.x * blockDim.x + threadIdx.x;
    if (i < n) g_dinv[i] = rsqrtf((float)(g_cnt[i] + 1));
}

__global__ void wconv(const float* __restrict__ W1, const float* __restrict__ W2) {
    int i = blockIdx.x * blockDim.x + threadIdx.x;
    if (i < F_IN * F_HID) {
        int k = i / F_HID, nn = i % F_HID;
        g_w1h[nn * F_IN + k] = __float2half_rn(W1[i]);
    }
    if (i < F_HID * F_OUT) {
        int k = i / F_OUT, nn = i % F_OUT;
        g_w2h[nn * F_HID + k] = __float2half_rn(W2[i]);
    }
}

#define ASTR 40   // fp16 row stride in smem (80B: (20r)%32 banks distinct -> LDSM clean)

// ---------------- layer-1 GEMM (fp16 TC, double-buffered, ldmatrix, fp8 out) -----
__global__ void __launch_bounds__(256, 2)
gemm1_mma(const float* __restrict__ A, uint8_t* __restrict__ C, int M) {
    __shared__ __align__(16) __half Ah[2][128 * ASTR];
    __shared__ __align__(16) __half Bh[2][128 * ASTR];

    const int tid = threadIdx.x;
    const int wid = tid >> 5;
    const int lane = tid & 31;
    const int warpM = (wid >> 2) * 64;
    const int warpN = (wid & 3) * 32;
    const int rowBase = blockIdx.x * 128;
    const int grp = lane >> 2;
    const int qid = lane & 3;
    constexpr int NT = F_IN / 32;

    const int a_row = (lane & 7) + ((lane >> 3) & 1) * 8;
    const int a_col = (lane >> 4) * 8;
    const int b_row = (lane & 7) + (lane >> 4) * 8;
    const int b_col = ((lane >> 3) & 1) * 8;
    const uint32_t aBase0 = (uint32_t)__cvta_generic_to_shared(&Ah[0][0]);
    const uint32_t aBase1 = (uint32_t)__cvta_generic_to_shared(&Ah[1][0]);
    const uint32_t bBase0 = (uint32_t)__cvta_generic_to_shared(&Bh[0][0]);
    const uint32_t bBase1 = (uint32_t)__cvta_generic_to_shared(&Bh[1][0]);

    int ar[4], ac[4];
#pragma unroll
    for (int t = 0; t < 4; t++) {
        int idx = tid + t * 256;
        ar[t] = idx >> 3;
        ac[t] = (idx & 7) * 4;
    }
    int bn[2], bk[2];
#pragma unroll
    for (int t = 0; t < 2; t++) {
        int idx = tid + t * 256;
        bn[t] = idx >> 2;
        bk[t] = (idx & 3) * 8;
    }

    float acc[4][4][4];
#pragma unroll
    for (int mi = 0; mi < 4; mi++)
#pragma unroll
        for (int nj = 0; nj < 4; nj++)
#pragma unroll
            for (int q = 0; q < 4; q++) acc[mi][nj][q] = 0.f;

    {
#pragma unroll
        for (int t = 0; t < 4; t++) {
            int gr = rowBase + ar[t];
            float4 v = make_float4(0.f, 0.f, 0.f, 0.f);
            if (gr < M) v = *(const float4*)&A[(size_t)gr * F_IN + ac[t]];
            __half2 p0 = __floats2half2_rn(v.x, v.y);
            __half2 p1 = __floats2half2_rn(v.z, v.w);
            uint32_t* ph = (uint32_t*)&Ah[0][ar[t] * ASTR + ac[t]];
            ph[0] = *(uint32_t*)&p0;
            ph[1] = *(uint32_t*)&p1;
        }
#pragma unroll
        for (int t = 0; t < 2; t++)
            *(int4*)&Bh[0][bn[t] * ASTR + bk[t]] = *(const int4*)&g_w1h[bn[t] * F_IN + bk[t]];
    }
    __syncthreads();

    for (int kt = 0; kt < NT; kt++) {
        const int cur = kt & 1;
        const int k1 = (kt + 1) * 32;
        const uint32_t aB = cur ? aBase1 : aBase0;
        const uint32_t bB = cur ? bBase1 : bBase0;

        float4 vA[4];
        int4 vB[2];
        if (kt + 1 < NT) {
#pragma unroll
            for (int t = 0; t < 4; t++) {
                int gr = rowBase + ar[t];
                vA[t] = make_float4(0.f, 0.f, 0.f, 0.f);
                if (gr < M) vA[t] = *(const float4*)&A[(size_t)gr * F_IN + k1 + ac[t]];
            }
#pragma unroll
            for (int t = 0; t < 2; t++)
                vB[t] = *(const int4*)&g_w1h[bn[t] * F_IN + k1 + bk[t]];
        }

#pragma unroll
        for (int ks = 0; ks < 2; ks++) {
            const int kst = ks * 16;
            uint32_t ah[4][4];
#pragma unroll
            for (int mi = 0; mi < 4; mi++) {
                uint32_t addr = aB + (uint32_t)(((warpM + mi * 16 + a_row) * ASTR
                                                 + kst + a_col) * 2);
                ldsm_x4(ah[mi][0], ah[mi][1], ah[mi][2], ah[mi][3], addr);
            }
            uint32_t bh[4][2];
#pragma unroll
            for (int njp = 0; njp < 2; njp++) {
                uint32_t addr = bB + (uint32_t)(((warpN + njp * 16 + b_row) * ASTR
                                                 + kst + b_col) * 2);
                ldsm_x4(bh[2 * njp][0], bh[2 * njp][1],
                        bh[2 * njp + 1][0], bh[2 * njp + 1][1], addr);
            }
#pragma unroll
            for (int mi = 0; mi < 4; mi++)
#pragma unroll
                for (int nj = 0; nj < 4; nj++)
                    mma_f16(acc[mi][nj], ah[mi], bh[nj]);
        }

        if (kt + 1 < NT) {
            const int nxt = cur ^ 1;
#pragma unroll
            for (int t = 0; t < 4; t++) {
                __half2 p0 = __floats2half2_rn(vA[t].x, vA[t].y);
                __half2 p1 = __floats2half2_rn(vA[t].z, vA[t].w);
                uint32_t* ph = (uint32_t*)&Ah[nxt][ar[t] * ASTR + ac[t]];
                ph[0] = *(uint32_t*)&p0;
                ph[1] = *(uint32_t*)&p1;
            }
#pragma unroll
            for (int t = 0; t < 2; t++)
                *(int4*)&Bh[nxt][bn[t] * ASTR + bk[t]] = vB[t];
            __syncthreads();
        }
    }

    // ---- epilogue: store e4m3 (unscaled) ----
#pragma unroll
    for (int mi = 0; mi < 4; mi++) {
        int r0 = rowBase + warpM + mi * 16 + grp;
        int r1 = r0 + 8;
#pragma unroll
        for (int nj = 0; nj < 4; nj++) {
            int c = warpN + nj * 8 + qid * 2;
            if (r0 < M)
                *(uint16_t*)&C[(size_t)r0 * F_HID + c] =
                    pack_e4m3x2(acc[mi][nj][0], acc[mi][nj][1]);
            if (r1 < M)
                *(uint16_t*)&C[(size_t)r1 * F_HID + c] =
                    pack_e4m3x2(acc[mi][nj][2], acc[mi][nj][3]);
        }
    }
}

// ---------------- layer-2 GEMM (fp16 TC, chunked, ldmatrix, fp16 out) ------------
__global__ void __launch_bounds__(256, 2)
gemm2_mma(__half* __restrict__ C, int rowOff, int rowEnd) {
    __shared__ __align__(16) __half Ah[128 * ASTR];
    __shared__ __align__(16) __half Bh[64 * ASTR];

    const int tid = threadIdx.x;
    const int wid = tid >> 5;
    const int lane = tid & 31;
    const int warpM = (wid >> 2) * 64;
    const int warpN = (wid & 3) * 16;
    const int rowBase = rowOff + blockIdx.x * 128;
    const int grp = lane >> 2;
    const int qid = lane & 3;

    const int a_row = (lane & 7) + ((lane >> 3) & 1) * 8;
    const int a_col = (lane >> 4) * 8;
    const int b_row = (lane & 7) + (lane >> 4) * 8;
    const int b_col = ((lane >> 3) & 1) * 8;
    const uint32_t aBase = (uint32_t)__cvta_generic_to_shared(&Ah[0]);
    const uint32_t bBase = (uint32_t)__cvta_generic_to_shared(&Bh[0]);

    float acc[4][2][4];
#pragma unroll
    for (int mi = 0; mi < 4; mi++)
#pragma unroll
        for (int nj = 0; nj < 2; nj++)
#pragma unroll
            for (int q = 0; q < 4; q++) acc[mi][nj][q] = 0.f;

    for (int k0 = 0; k0 < F_HID; k0 += 32) {
#pragma unroll
        for (int t = 0; t < 2; t++) {
            int idx = tid + t * 256;
            int r = idx >> 2;
            int koff = (idx & 3) * 8;
            int gr = rowBase + r;
            uint4 v = make_uint4(0u, 0u, 0u, 0u);
            if (gr < rowEnd) v = *(const uint4*)&g_h16[(size_t)gr * F_HID + k0 + koff];
            *(uint4*)&Ah[r * ASTR + koff] = v;
        }
        if (tid < 256) {
            int nrow = tid >> 2;
            int koff = (tid & 3) * 8;
            *(int4*)&Bh[nrow * ASTR + koff] = *(const int4*)&g_w2h[nrow * F_HID + k0 + koff];
        }
        __syncthreads();

#pragma unroll
        for (int ks = 0; ks < 2; ks++) {
            const int kst = ks * 16;
            uint32_t ah[4][4];
#pragma unroll
            for (int mi = 0; mi < 4; mi++) {
                uint32_t addr = aBase + (uint32_t)(((warpM + mi * 16 + a_row) * ASTR
                                                    + kst + a_col) * 2);
                ldsm_x4(ah[mi][0], ah[mi][1], ah[mi][2], ah[mi][3], addr);
            }
            uint32_t bh[2][2];
            {
                uint32_t addr = bBase + (uint32_t)(((warpN + b_row) * ASTR
                                                    + kst + b_col) * 2);
                ldsm_x4(bh[0][0], bh[0][1], bh[1][0], bh[1][1], addr);
            }
#pragma unroll
            for (int mi = 0; mi < 4; mi++)
#pragma unroll
                for (int nj = 0; nj < 2; nj++)
                    mma_f16(acc[mi][nj], ah[mi], bh[nj]);
        }
        __syncthreads();
    }

#pragma unroll
    for (int mi = 0; mi < 4; mi++) {
        int r0 = rowBase + warpM + mi * 16 + grp;
        int r1 = r0 + 8;
        float s0 = (r0 < rowEnd) ? g_dinv[r0] : 0.f;
        float s1 = (r1 < rowEnd) ? g_dinv[r1] : 0.f;
#pragma unroll
        for (int nj = 0; nj < 2; nj++) {
            int c = warpN + nj * 8 + qid * 2;
            if (r0 < rowEnd)
                *(__half2*)&C[(size_t)r0 * F_OUT + c] =
                    __floats2half2_rn(acc[mi][nj][0] * s0, acc[mi][nj][1] * s0);
            if (r1 < rowEnd)
                *(__half2*)&C[(size_t)r1 * F_OUT + c] =
                    __floats2half2_rn(acc[mi][nj][2] * s1, acc[mi][nj][3] * s1);
        }
    }
}

// ---------------- gather layer 1: 8 lanes/node, fp8 rows, half2 math -------------
__global__ void gather1(const float* __restrict__ b1, int nodeOff, int nodeEnd) {
    size_t t = (size_t)blockIdx.x * blockDim.x + threadIdx.x;
    int node = nodeOff + (int)(t >> 3);
    int l = threadIdx.x & 7;
    if (node >= nodeEnd) return;
    const uint4* xw1 = (const uint4*)g_xw1q;
    float di = g_dinv[node];
    __half2 vh[8], bh2[8];
    float acc[16];
    dq8h(xw1[(size_t)node * 8 + l], vh);
#pragma unroll
    for (int q = 0; q < 8; q++) {
        float2 f = __half22float2(vh[q]);
        acc[2 * q]     = f.x * di;
        acc[2 * q + 1] = f.y * di;
    }
    int ne = g_cnt[node];
    if (ne > BCAP) ne = BCAP;
    int base = node * BCAP;
    int i = 0;
    for (; i + 4 <= ne; i += 4) {
        int4 s4 = *(const int4*)&g_bucket[base + i];
        uint4 r0 = xw1[(size_t)s4.x * 8 + l];
        uint4 r1 = xw1[(size_t)s4.y * 8 + l];
        uint4 r2 = xw1[(size_t)s4.z * 8 + l];
        uint4 r3 = xw1[(size_t)s4.w * 8 + l];
        __half2 d0 = __float2half2_rn(g_dinv[s4.x]);
        __half2 d1 = __float2half2_rn(g_dinv[s4.y]);
        __half2 d2 = __float2half2_rn(g_dinv[s4.z]);
        __half2 d3 = __float2half2_rn(g_dinv[s4.w]);
        dq8h(r0, bh2);
#pragma unroll
        for (int q = 0; q < 8; q++) bh2[q] = __hmul2(bh2[q], d0);
        dq8h(r1, vh);
#pragma unroll
        for (int q = 0; q < 8; q++) bh2[q] = __hfma2(vh[q], d1, bh2[q]);
        dq8h(r2, vh);
#pragma unroll
        for (int q = 0; q < 8; q++) bh2[q] = __hfma2(vh[q], d2, bh2[q]);
        dq8h(r3, vh);
#pragma unroll
        for (int q = 0; q < 8; q++) bh2[q] = __hfma2(vh[q], d3, bh2[q]);
        // flush 4-edge half2 block into fp32 accumulators
#pragma unroll
        for (int q = 0; q < 8; q++) {
            float2 f = __half22float2(bh2[q]);
            acc[2 * q]     += f.x;
            acc[2 * q + 1] += f.y;
        }
    }
    for (; i < ne; i++) {
        int s = g_bucket[base + i];
        float ds = g_dinv[s];
        dq8h(xw1[(size_t)s * 8 + l], vh);
#pragma unroll
        for (int q = 0; q < 8; q++) {
            float2 f = __half22float2(vh[q]);
            acc[2 * q]     = fmaf(ds, f.x, acc[2 * q]);
            acc[2 * q + 1] = fmaf(ds, f.y, acc[2 * q + 1]);
        }
    }
    float bf[16];
#pragma unroll
    for (int k = 0; k < 4; k++) {
        float4 bv = ((const float4*)b1)[l * 4 + k];
        bf[k * 4 + 0] = bv.x; bf[k * 4 + 1] = bv.y;
        bf[k * 4 + 2] = bv.z; bf[k * 4 + 3] = bv.w;
    }
    __half2 out[8];
#pragma unroll
    for (int q = 0; q < 8; q++) {
        float h0 = fmaxf(fmaf(acc[2 * q], di, bf[2 * q]), 0.f);
        float h1 = fmaxf(fmaf(acc[2 * q + 1], di, bf[2 * q + 1]), 0.f);
        out[q] = __floats2half2_rn(h0, h1);
    }
    uint4* dst = (uint4*)&g_h16[(size_t)node * F_HID + l * 16];
    dst[0] = *(uint4*)&out[0];
    dst[1] = *(uint4*)&out[4];
}

// ---------------- gather layer 2: 8 lanes/node, fp16 rows, HADD2 blocks ----------
__global__ void gather2_lsm(const float* __restrict__ b2, float* __restrict__ out, int n) {
    size_t t = (size_t)blockIdx.x * blockDim.x + threadIdx.x;
    int node = (int)(t >> 3);
    int l = threadIdx.x & 7;
    if (node >= n) return;
    const uint4* xw2 = (const uint4*)g_xw2h;   // 8 uint4 per row (8 halfs each)
    float acc[8];
    {
        uint4 u = xw2[(size_t)node * 8 + l];   // self (pre-scaled by dinv[row])
        __half2* p = (__half2*)&u;
#pragma unroll
        for (int q = 0; q < 4; q++) {
            float2 f = __half22float2(p[q]);
            acc[2 * q] = f.x; acc[2 * q + 1] = f.y;
        }
    }
    int ne = g_cnt[node];
    if (ne > BCAP) ne = BCAP;
    int base = node * BCAP;
    int i = 0;
    for (; i + 8 <= ne; i += 8) {
        int4 sa = *(const int4*)&g_bucket[base + i];
        int4 sb = *(const int4*)&g_bucket[base + i + 4];
        uint4 r0 = xw2[(size_t)sa.x * 8 + l];
        uint4 r1 = xw2[(size_t)sa.y * 8 + l];
        uint4 r2 = xw2[(size_t)sa.z * 8 + l];
        uint4 r3 = xw2[(size_t)sa.w * 8 + l];
        uint4 r4 = xw2[(size_t)sb.x * 8 + l];
        uint4 r5 = xw2[(size_t)sb.y * 8 + l];
        uint4 r6 = xw2[(size_t)sb.z * 8 + l];
        uint4 r7 = xw2[(size_t)sb.w * 8 + l];
        __half2* p0 = (__half2*)&r0; __half2* p1 = (__half2*)&r1;
        __half2* p2 = (__half2*)&r2; __half2* p3 = (__half2*)&r3;
        __half2* p4 = (__half2*)&r4; __half2* p5 = (__half2*)&r5;
        __half2* p6 = (__half2*)&r6; __half2* p7 = (__half2*)&r7;
#pragma unroll
        for (int q = 0; q < 4; q++) {
            __half2 s01 = __hadd2(p0[q], p1[q]);
            __half2 s23 = __hadd2(p2[q], p3[q]);
            __half2 s45 = __hadd2(p4[q], p5[q]);
            __half2 s67 = __hadd2(p6[q], p7[q]);
            __half2 s = __hadd2(__hadd2(s01, s23), __hadd2(s45, s67));
            float2 f = __half22float2(s);
            acc[2 * q]     += f.x;
            acc[2 * q + 1] += f.y;
        }
    }
    for (; i < ne; i++) {
        uint4 u = xw2[(size_t)g_bucket[base + i] * 8 + l];
        __half2* p = (__half2*)&u;
#pragma unroll
        for (int q = 0; q < 4; q++) {
            float2 f = __half22float2(p[q]);
            acc[2 * q] += f.x; acc[2 * q + 1] += f.y;
        }
    }
    float di = g_dinv[node];
    float4 ba = ((const float4*)b2)[l * 2];
    float4 bb = ((const float4*)b2)[l * 2 + 1];
    float bf[8] = {ba.x, ba.y, ba.z, ba.w, bb.x, bb.y, bb.z, bb.w};
    float z[8];
    float m = -1e30f;
#pragma unroll
    for (int q = 0; q < 8; q++) {
        z[q] = fmaf(acc[q], di, bf[q]);
        m = fmaxf(m, z[q]);
    }
#pragma unroll
    for (int o = 4; o; o >>= 1) m = fmaxf(m, __shfl_xor_sync(0xffffffffu, m, o));
    float s = 0.f;
#pragma unroll
    for (int q = 0; q < 8; q++) s += expf(z[q] - m);
#pragma unroll
    for (int o = 4; o; o >>= 1) s += __shfl_xor_sync(0xffffffffu, s, o);
    float lse = m + logf(s);
    float4 o0 = make_float4(z[0] - lse, z[1] - lse, z[2] - lse, z[3] - lse);
    float4 o1 = make_float4(z[4] - lse, z[5] - lse, z[6] - lse, z[7] - lse);
    *(float4*)&out[(size_t)node * F_OUT + l * 8] = o0;
    *(float4*)&out[(size_t)node * F_OUT + l * 8 + 4] = o1;
}

// ---------------- launch ----------------------------------------------------------
extern "C" void kernel_launch(void* const* d_in, const int* in_sizes, int n_in,
                              void* d_out, int out_size) {
    const float* x  = (const float*)d_in[0];
    const float* W1 = (const float*)d_in[1];
    const float* b1 = (const float*)d_in[2];
    const float* W2 = (const float*)d_in[3];
    const float* b2 = (const float*)d_in[4];
    const int* ei_words = (const int*)d_in[5];

    const int n = in_sizes[0] / F_IN;   // 100000
    const int E = in_sizes[5] / 2;      // 3200000

    uint8_t* xw1p;
    __half* xw2p;
    cudaGetSymbolAddress((void**)&xw1p, g_xw1q);
    cudaGetSymbolAddress((void**)&xw2p, g_xw2h);

    static cudaStream_t sB = nullptr;
    static cudaEvent_t evFork = nullptr, evJoin = nullptr;
    static cudaEvent_t evA1 = nullptr, evA2 = nullptr, evB = nullptr;
    if (!sB) {
        cudaStreamCreateWithFlags(&sB, cudaStreamNonBlocking);
        cudaEventCreateWithFlags(&evFork, cudaEventDisableTiming);
        cudaEventCreateWithFlags(&evJoin, cudaEventDisableTiming);
        cudaEventCreateWithFlags(&evA1, cudaEventDisableTiming);
        cudaEventCreateWithFlags(&evA2, cudaEventDisableTiming);
        cudaEventCreateWithFlags(&evB, cudaEventDisableTiming);
    }

    // Fork: edge pipeline overlapped with weight conversion + layer-1 GEMM.
    cudaEventRecord(evFork, 0);
    cudaStreamWaitEvent(sB, evFork, 0);

    init_kernel<<<(NN + 255) / 256, 256, 0, sB>>>(ei_words);
    fill_kernel<<<(E / 2 + 255) / 256, 256, 0, sB>>>(ei_words, E);
    dinv_kernel<<<(n + 255) / 256, 256, 0, sB>>>(n);
    cudaEventRecord(evJoin, sB);

    wconv<<<(F_IN * F_HID + 255) / 256, 256>>>(W1, W2);
    gemm1_mma<<<(n + 127) / 128, 256>>>(x, xw1p, n);

    cudaStreamWaitEvent(0, evJoin, 0);

    // ---- 3-chunk gather1 / gemm2 pipeline ----
    const int c1 = ((n / 3 + 127) / 128) * 128;      // 33408
    const int c2 = 2 * c1;                            // 66816
    {
        size_t th = (size_t)c1 * 8;
        gather1<<<(unsigned)((th + 255) / 256), 256>>>(b1, 0, c1);
    }
    cudaEventRecord(evA1, 0);
    cudaStreamWaitEvent(sB, evA1, 0);
    gemm2_mma<<<(c1 + 127) / 128, 256, 0, sB>>>(xw2p, 0, c1);
    {
        size_t th = (size_t)(c2 - c1) * 8;
        gather1<<<(unsigned)((th + 255) / 256), 256>>>(b1, c1, c2);
    }
    cudaEventRecord(evA2, 0);
    cudaStreamWaitEvent(sB, evA2, 0);
    gemm2_mma<<<(c2 - c1 + 127) / 128, 256, 0, sB>>>(xw2p, c1, c2);
    cudaEventRecord(evB, sB);
    {
        size_t th = (size_t)(n - c2) * 8;
        gather1<<<(unsigned)((th + 255) / 256), 256>>>(b1, c2, n);
    }
    gemm2_mma<<<(n - c2 + 127) / 128, 256>>>(xw2p, c2, n);
    cudaStreamWaitEvent(0, evB, 0);

    {
        size_t th = (size_t)n * 8;
        gather2_lsm<<<(unsigned)((th + 255) / 256), 256>>>(b2, (float*)d_out, n);
    }
}